// round 6
// baseline (speedup 1.0000x reference)
#include <cuda_runtime.h>
#include <cuda_fp16.h>

#define NR   2097152
#define K    7
#define GRID 148                 // <= SM count: all blocks co-resident (1 CTA/SM via smem)
#define TPB  768
#define RPB  14172               // rows per block (mult of 4); last block: 13868
#define NIT  50

static __device__ double   g_S[NIT + 1][8];   // per-iteration reduction slots
static __device__ unsigned g_bar;             // grid barrier counter (monotonic)

__constant__ double c_Pb[K] = {0.17, 0.14, 0.15, 0.12, 0.05, 0.13, 0.24};

struct Scratch {
    double warp[TPB / 32][K];   // block reduction staging
    double b[K];                // current b (double, exact chain)
    double bp[K];               // previous b
    double d2[K];               // per-component squared diffs
};

#define DYN_SMEM ((size_t)RPB * 16 + sizeof(Scratch))

// MUFU reciprocal (1 ulp) — short chain, off the FMA pipe
__device__ __forceinline__ float rcpa(float x) {
    float y;
    asm("rcp.approx.f32 %0, %1;" : "=f"(y) : "f"(x));
    return y;
}

// ---------------------------------------------------------------------------
// Grid barrier: all GRID blocks resident, monotonic target.
// ---------------------------------------------------------------------------
__device__ __forceinline__ void grid_bar(unsigned target) {
    __syncthreads();
    if (threadIdx.x == 0) {
        atomicAdd(&g_bar, 1u);
        while (atomicAdd(&g_bar, 0u) < target) { }
    }
    __syncthreads();
}

// ---------------------------------------------------------------------------
// Block-reduce K fp32 partials -> double -> atomicAdd into g_S[it]
// ---------------------------------------------------------------------------
__device__ __forceinline__ void publish(Scratch* sc, float acc[K], int it) {
    int tid = threadIdx.x;
#pragma unroll
    for (int j = 0; j < K; j++) {
#pragma unroll
        for (int off = 16; off > 0; off >>= 1)
            acc[j] += __shfl_down_sync(0xffffffffu, acc[j], off);
    }
    int w = tid >> 5;
    if ((tid & 31) == 0) {
#pragma unroll
        for (int j = 0; j < K; j++) sc->warp[w][j] = (double)acc[j];
    }
    __syncthreads();
    if (tid < K) {
        double s = 0.0;
#pragma unroll
        for (int ww = 0; ww < TPB / 32; ww++) s += sc->warp[ww][tid];
        atomicAdd(&g_S[it][tid], s);
        __threadfence();   // release our g_S contribution before barrier arrive
    }
}

// ---------------------------------------------------------------------------
// b update, computed redundantly & identically by every block. Returns err.
// ---------------------------------------------------------------------------
__device__ __forceinline__ double b_update(Scratch* sc, int it, int first) {
    int tid = threadIdx.x;
    __threadfence();           // acquire side for g_S reads
    if (tid < K) {
        double S = g_S[it][tid];                  // fresh slot: never in this L1
        double v = (double)NR * c_Pb[tid] / S;    // b_j = Pb_j / (Q^T a)_j
        double nb = pow(v, 1.0 / 1.1);            // SEMI_USE exponent
        double old = sc->b[tid];
        sc->bp[tid] = old;
        sc->b[tid] = nb;
        double d = nb - old;
        sc->d2[tid] = d * d;
    }
    __syncthreads();
    double e2 = sc->d2[0] + sc->d2[1] + sc->d2[2] + sc->d2[3]
              + sc->d2[4] + sc->d2[5] + sc->d2[6];
    if (first) e2 += 0.015625;   // b[7]: 1/8 -> 0 on iteration 1
    return sqrt(e2);
}

// ---------------------------------------------------------------------------
__global__ void k_init() {
    int t = threadIdx.x;
    if (t == 0) g_bar = 0u;
    double* p = &g_S[0][0];
    for (int i = t; i < (NIT + 1) * 8; i += blockDim.x) p[i] = 0.0;
}

// ---------------------------------------------------------------------------
// One dot/rcp/accum step for a row held in a uint4 of 8 halves
// ---------------------------------------------------------------------------
__device__ __forceinline__ void row_step(uint4 v, const float bf[K], float acc[K]) {
    const __half2* h = reinterpret_cast<const __half2*>(&v);
    float2 f0 = __half22float2(h[0]);
    float2 f1 = __half22float2(h[1]);
    float2 f2 = __half22float2(h[2]);
    float2 f3 = __half22float2(h[3]);
    float dot = f0.x * bf[0];
    dot = fmaf(f0.y, bf[1], dot);
    dot = fmaf(f1.x, bf[2], dot);
    dot = fmaf(f1.y, bf[3], dot);
    dot = fmaf(f2.x, bf[4], dot);
    dot = fmaf(f2.y, bf[5], dot);
    dot = fmaf(f3.x, bf[6], dot);
    float inv = rcpa(dot);                 // row max of E is 1 -> dot > 0
    acc[0] = fmaf(f0.x, inv, acc[0]);
    acc[1] = fmaf(f0.y, inv, acc[1]);
    acc[2] = fmaf(f1.x, inv, acc[2]);
    acc[3] = fmaf(f1.y, inv, acc[3]);
    acc[4] = fmaf(f2.x, inv, acc[4]);
    acc[5] = fmaf(f2.y, inv, acc[5]);
    acc[6] = fmaf(f3.x, inv, acc[6]);
}

// ---------------------------------------------------------------------------
// Persistent fused kernel: pre + all Sinkhorn iterations + final plan.
// E (fp16, 16 B/row) lives in this block's SMEM for the whole run.
// ---------------------------------------------------------------------------
__global__ void __launch_bounds__(TPB, 1)
k_main(const float* __restrict__ P, float* __restrict__ out) {
    extern __shared__ __align__(16) unsigned char dyn[];
    uint4*   Es = reinterpret_cast<uint4*>(dyn);                 // [nrows]
    Scratch* sc = reinterpret_cast<Scratch*>(dyn + (size_t)RPB * 16);

    const int tid   = threadIdx.x;
    const int base  = blockIdx.x * RPB;
    const int nrows = min(RPB, NR - base);
    const int ngrp  = nrows >> 2;          // groups of 4 rows (exact)
    unsigned phase = 0;

    if (tid < K) { sc->b[tid] = 0.125; sc->bp[tid] = 0.125; }
    __syncthreads();

    // ---- Phase A: build E in SMEM + iteration-1 partials --------------------
    // Iter 1 closed form: w_i = 8 r_i / (r_i*sumE_i + 1), r_i = s1^-10
    float acc[K];
#pragma unroll
    for (int j = 0; j < K; j++) acc[j] = 0.f;

    for (int g = tid; g < ngrp; g += TPB) {
        const uint4* ps = reinterpret_cast<const uint4*>(P + (size_t)(base + (g << 2)) * K);
        uint4 q[7];
#pragma unroll
        for (int i = 0; i < 7; i++) q[i] = ps[i];   // 4 rows = 28 floats, coalesced
        const float* pf = reinterpret_cast<const float*>(q);
#pragma unroll
        for (int r = 0; r < 4; r++) {
            const float* pr = pf + r * 7;
            float m = pr[0];
#pragma unroll
            for (int j = 1; j < K; j++) m = fmaxf(m, pr[j]);
            float t[K], s1 = 0.f;
#pragma unroll
            for (int j = 0; j < K; j++) {
                t[j] = __expf(pr[j] - m);          // MUFU EX2
                s1 += t[j];
            }
            float E[K], sE = 0.f;
#pragma unroll
            for (int j = 0; j < K; j++) {
                float t2 = t[j] * t[j], t4 = t2 * t2, t8 = t4 * t4;
                E[j] = t8 * t2;                    // exp(10*(p-m)) = t^10
                sE += E[j];
            }
            __half2 h0 = __floats2half2_rn(E[0], E[1]);
            __half2 h1 = __floats2half2_rn(E[2], E[3]);
            __half2 h2 = __floats2half2_rn(E[4], E[5]);
            __half2 h3 = __floats2half2_rn(E[6], 0.f);
            uint4 u;
            u.x = *reinterpret_cast<unsigned*>(&h0);
            u.y = *reinterpret_cast<unsigned*>(&h1);
            u.z = *reinterpret_cast<unsigned*>(&h2);
            u.w = *reinterpret_cast<unsigned*>(&h3);
            Es[(g << 2) + r] = u;

            float s2 = s1 * s1, s4 = s2 * s2, s8 = s4 * s4;
            float r10 = rcpa(s8 * s2);                        // s1^-10
            float w = 8.f * r10 * rcpa(fmaf(r10, sE, 1.f));
#pragma unroll
            for (int j = 0; j < K; j++) acc[j] = fmaf(w, E[j], acc[j]);
        }
    }
    publish(sc, acc, 1);
    grid_bar(GRID * (++phase));
    int it = 1;
    double err = b_update(sc, 1, 1);

    // ---- Iterations 2..50: SMEM-only passes, 4-way ILP ----------------------
    // NOTE: 4*TPB is NOT a power of two; compute the tail split by division.
    const int nmain = nrows - nrows % (4 * TPB);
    while (err > 1e-6 && it < NIT) {
        it++;
        float bf[K];
#pragma unroll
        for (int j = 0; j < K; j++) bf[j] = (float)sc->b[j];
        float a2[K];
#pragma unroll
        for (int j = 0; j < K; j++) a2[j] = 0.f;

        for (int idx = tid; idx < nmain; idx += 4 * TPB) {
            uint4 v0 = Es[idx];
            uint4 v1 = Es[idx + TPB];
            uint4 v2 = Es[idx + 2 * TPB];
            uint4 v3 = Es[idx + 3 * TPB];
            row_step(v0, bf, a2);
            row_step(v1, bf, a2);
            row_step(v2, bf, a2);
            row_step(v3, bf, a2);
        }
        for (int idx = nmain + tid; idx < nrows; idx += TPB)
            row_step(Es[idx], bf, a2);

        publish(sc, a2, it);
        grid_bar(GRID * (++phase));
        err = b_update(sc, it, 0);
    }

    // ---- Final: plan_ij = E_ij * bn_j / (E_i . bp), from SMEM ---------------
    float bn[K], bp[K];
#pragma unroll
    for (int j = 0; j < K; j++) { bn[j] = (float)sc->b[j]; bp[j] = (float)sc->bp[j]; }

    for (int g = tid; g < ngrp; g += TPB) {
        float4 o[7];
        float* of = reinterpret_cast<float*>(o);
#pragma unroll
        for (int r = 0; r < 4; r++) {
            uint4 v = Es[(g << 2) + r];
            const __half2* h = reinterpret_cast<const __half2*>(&v);
            float2 f0 = __half22float2(h[0]);
            float2 f1 = __half22float2(h[1]);
            float2 f2 = __half22float2(h[2]);
            float2 f3 = __half22float2(h[3]);
            float dot = f0.x * bp[0];
            dot = fmaf(f0.y, bp[1], dot);
            dot = fmaf(f1.x, bp[2], dot);
            dot = fmaf(f1.y, bp[3], dot);
            dot = fmaf(f2.x, bp[4], dot);
            dot = fmaf(f2.y, bp[5], dot);
            dot = fmaf(f3.x, bp[6], dot);
            float inv = rcpa(dot);
            of[r * 7 + 0] = f0.x * bn[0] * inv;
            of[r * 7 + 1] = f0.y * bn[1] * inv;
            of[r * 7 + 2] = f1.x * bn[2] * inv;
            of[r * 7 + 3] = f1.y * bn[3] * inv;
            of[r * 7 + 4] = f2.x * bn[4] * inv;
            of[r * 7 + 5] = f2.y * bn[5] * inv;
            of[r * 7 + 6] = f3.x * bn[6] * inv;
        }
        float4* od = reinterpret_cast<float4*>(out + (size_t)(base + (g << 2)) * K);
#pragma unroll
        for (int i = 0; i < 7; i++) od[i] = o[i];   // 4 rows = 7 STG.128
    }
}

// ---------------------------------------------------------------------------
extern "C" void kernel_launch(void* const* d_in, const int* in_sizes, int n_in,
                              void* d_out, int out_size) {
    const float* P = (const float*)d_in[0];
    float* out = (float*)d_out;
    (void)in_sizes; (void)n_in; (void)out_size;

    static int configured = 0;
    if (!configured) {
        cudaFuncSetAttribute(k_main, cudaFuncAttributeMaxDynamicSharedMemorySize,
                             (int)DYN_SMEM);
        configured = 1;
    }
    k_init<<<1, 512>>>();                       // reset barrier/reduction state
    k_main<<<GRID, TPB, DYN_SMEM>>>(P, out);    // everything else, one launch
}

// round 7
// speedup vs baseline: 1.8316x; 1.8316x over previous
#include <cuda_runtime.h>
#include <cuda_fp16.h>

#define NR   2097152
#define K    7
#define GRID 148                 // <= SM count: all blocks co-resident (1 CTA/SM via smem)
#define TPB  512                 // 4*TPB = 2048 (power of two -> mask tail is safe)
#define NW   (TPB / 32)
#define RPB  14172               // rows per block (mult of 4); last block: 13868
#define NIT  50

static __device__ float    g_S[NIT + 1][8];   // per-iteration fp32 reduction slots
static __device__ unsigned g_bar;             // grid barrier counter (monotonic)

// NR * Pb_j, exact products of the prior
__constant__ float c_NPb[K] = {
    (float)(2097152.0 * 0.17), (float)(2097152.0 * 0.14),
    (float)(2097152.0 * 0.15), (float)(2097152.0 * 0.12),
    (float)(2097152.0 * 0.05), (float)(2097152.0 * 0.13),
    (float)(2097152.0 * 0.24)
};

#define DYN_SMEM ((size_t)RPB * 16 + NW * K * sizeof(float))

// MUFU reciprocal (1 ulp)
__device__ __forceinline__ float rcpa(float x) {
    float y;
    asm("rcp.approx.f32 %0, %1;" : "=f"(y) : "f"(x));
    return y;
}

// ---------------------------------------------------------------------------
// Grid barrier: all GRID blocks resident, monotonic target. Volatile-load spin
// (no RMW contention); release fence before arrive, acquire fence after.
// ---------------------------------------------------------------------------
__device__ __forceinline__ void grid_bar(unsigned target) {
    __syncthreads();
    if (threadIdx.x == 0) {
        __threadfence();                       // release our g_S atomics
        atomicAdd(&g_bar, 1u);
        while (*(volatile unsigned*)&g_bar < target) { }
        __threadfence();                       // acquire side
    }
    __syncthreads();
}

// ---------------------------------------------------------------------------
// Block-reduce K fp32 partials -> float atomicAdd into g_S[it]
// ---------------------------------------------------------------------------
__device__ __forceinline__ void publish(float* swarp, float acc[K], int it) {
    int tid = threadIdx.x;
#pragma unroll
    for (int j = 0; j < K; j++) {
#pragma unroll
        for (int off = 16; off > 0; off >>= 1)
            acc[j] += __shfl_down_sync(0xffffffffu, acc[j], off);
    }
    int w = tid >> 5;
    if ((tid & 31) == 0) {
#pragma unroll
        for (int j = 0; j < K; j++) swarp[w * K + j] = acc[j];
    }
    __syncthreads();
    if (tid < K) {
        float s = 0.f;
#pragma unroll
        for (int ww = 0; ww < NW; ww++) s += swarp[ww * K + tid];
        atomicAdd(&g_S[it][tid], s);
    }
}

// ---------------------------------------------------------------------------
// Per-thread redundant b update (all threads identical inputs -> identical b).
// Returns err. Short fp32 chain: ldcg + fdividef + __powf.
// ---------------------------------------------------------------------------
__device__ __forceinline__ float b_update(int it, float bf[K], float bpf[K]) {
    const float FI = (float)(1.0 / 1.1);
    float e2 = 0.f;
#pragma unroll
    for (int j = 0; j < K; j++) {
        float S  = __ldcg(&g_S[it][j]);        // L2 read (atomics live in L2)
        float v  = __fdividef(c_NPb[j], S);    // b_j = Pb_j / (Q^T a)_j
        float nb = __powf(v, FI);              // SEMI_USE exponent
        float d  = nb - bf[j];
        e2 = fmaf(d, d, e2);
        bpf[j] = bf[j];
        bf[j]  = nb;
    }
    return sqrtf(e2);
}

// ---------------------------------------------------------------------------
__global__ void k_init() {
    int t = threadIdx.x;
    if (t == 0) g_bar = 0u;
    float* p = &g_S[0][0];
    for (int i = t; i < (NIT + 1) * 8; i += blockDim.x) p[i] = 0.f;
}

// ---------------------------------------------------------------------------
// One dot/rcp/accum step for a row held in a uint4 of 8 halves
// ---------------------------------------------------------------------------
__device__ __forceinline__ void row_step(uint4 v, const float bf[K], float acc[K]) {
    const __half2* h = reinterpret_cast<const __half2*>(&v);
    float2 f0 = __half22float2(h[0]);
    float2 f1 = __half22float2(h[1]);
    float2 f2 = __half22float2(h[2]);
    float2 f3 = __half22float2(h[3]);
    float dot = f0.x * bf[0];
    dot = fmaf(f0.y, bf[1], dot);
    dot = fmaf(f1.x, bf[2], dot);
    dot = fmaf(f1.y, bf[3], dot);
    dot = fmaf(f2.x, bf[4], dot);
    dot = fmaf(f2.y, bf[5], dot);
    dot = fmaf(f3.x, bf[6], dot);
    float inv = rcpa(dot);                 // row max of E is 1 -> dot > 0
    acc[0] = fmaf(f0.x, inv, acc[0]);
    acc[1] = fmaf(f0.y, inv, acc[1]);
    acc[2] = fmaf(f1.x, inv, acc[2]);
    acc[3] = fmaf(f1.y, inv, acc[3]);
    acc[4] = fmaf(f2.x, inv, acc[4]);
    acc[5] = fmaf(f2.y, inv, acc[5]);
    acc[6] = fmaf(f3.x, inv, acc[6]);
}

// ---------------------------------------------------------------------------
// Persistent fused kernel: pre + all Sinkhorn iterations + final plan.
// E (fp16, 16 B/row) lives in this block's SMEM for the whole run.
// ---------------------------------------------------------------------------
__global__ void __launch_bounds__(TPB, 1)
k_main(const float* __restrict__ P, float* __restrict__ out) {
    extern __shared__ __align__(16) unsigned char dyn[];
    uint4* Es    = reinterpret_cast<uint4*>(dyn);                 // [nrows]
    float* swarp = reinterpret_cast<float*>(dyn + (size_t)RPB * 16);

    const int tid   = threadIdx.x;
    const int base  = blockIdx.x * RPB;
    const int nrows = min(RPB, NR - base);
    const int ngrp  = nrows >> 2;          // groups of 4 rows (exact)
    unsigned phase = 0;

    float bf[K], bpf[K];
#pragma unroll
    for (int j = 0; j < K; j++) { bf[j] = 0.125f; bpf[j] = 0.125f; }

    // ---- Phase A: build E in SMEM + iteration-1 partials --------------------
    // Iter 1 closed form: w_i = 8 r_i / (r_i*sumE_i + 1), r_i = s1^-10
    float acc[K];
#pragma unroll
    for (int j = 0; j < K; j++) acc[j] = 0.f;

    for (int g = tid; g < ngrp; g += TPB) {
        const uint4* ps = reinterpret_cast<const uint4*>(P + (size_t)(base + (g << 2)) * K);
        uint4 q[7];
#pragma unroll
        for (int i = 0; i < 7; i++) q[i] = ps[i];   // 4 rows = 28 floats, coalesced
        const float* pf = reinterpret_cast<const float*>(q);
#pragma unroll
        for (int r = 0; r < 4; r++) {
            const float* pr = pf + r * 7;
            float m = pr[0];
#pragma unroll
            for (int j = 1; j < K; j++) m = fmaxf(m, pr[j]);
            float t[K], s1 = 0.f;
#pragma unroll
            for (int j = 0; j < K; j++) {
                t[j] = __expf(pr[j] - m);          // MUFU EX2
                s1 += t[j];
            }
            float E[K], sE = 0.f;
#pragma unroll
            for (int j = 0; j < K; j++) {
                float t2 = t[j] * t[j], t4 = t2 * t2, t8 = t4 * t4;
                E[j] = t8 * t2;                    // exp(10*(p-m)) = t^10
                sE += E[j];
            }
            __half2 h0 = __floats2half2_rn(E[0], E[1]);
            __half2 h1 = __floats2half2_rn(E[2], E[3]);
            __half2 h2 = __floats2half2_rn(E[4], E[5]);
            __half2 h3 = __floats2half2_rn(E[6], 0.f);
            uint4 u;
            u.x = *reinterpret_cast<unsigned*>(&h0);
            u.y = *reinterpret_cast<unsigned*>(&h1);
            u.z = *reinterpret_cast<unsigned*>(&h2);
            u.w = *reinterpret_cast<unsigned*>(&h3);
            Es[(g << 2) + r] = u;

            float s2 = s1 * s1, s4 = s2 * s2, s8 = s4 * s4;
            float r10 = rcpa(s8 * s2);                        // s1^-10
            float w = 8.f * r10 * rcpa(fmaf(r10, sE, 1.f));
#pragma unroll
            for (int j = 0; j < K; j++) acc[j] = fmaf(w, E[j], acc[j]);
        }
    }
    publish(swarp, acc, 1);
    grid_bar(GRID * (++phase));
    int it = 1;
    float err = b_update(1, bf, bpf);
    err = sqrtf(err * err + 0.015625f);    // b[7]: 1/8 -> 0 on iteration 1

    // ---- Iterations 2..50: SMEM-only passes, 4-way ILP ----------------------
    const int nmain = nrows & ~(4 * TPB - 1);   // 4*TPB = 2048, power of two
    while (err > 1e-6f && it < NIT) {
        it++;
        float a2[K];
#pragma unroll
        for (int j = 0; j < K; j++) a2[j] = 0.f;

        for (int idx = tid; idx < nmain; idx += 4 * TPB) {
            uint4 v0 = Es[idx];
            uint4 v1 = Es[idx + TPB];
            uint4 v2 = Es[idx + 2 * TPB];
            uint4 v3 = Es[idx + 3 * TPB];
            row_step(v0, bf, a2);
            row_step(v1, bf, a2);
            row_step(v2, bf, a2);
            row_step(v3, bf, a2);
        }
        for (int idx = nmain + tid; idx < nrows; idx += TPB)
            row_step(Es[idx], bf, a2);

        publish(swarp, a2, it);
        grid_bar(GRID * (++phase));
        err = b_update(it, bf, bpf);
    }

    // ---- Final: plan_ij = E_ij * bf_j / (E_i . bpf), from SMEM --------------
    for (int g = tid; g < ngrp; g += TPB) {
        float4 o[7];
        float* of = reinterpret_cast<float*>(o);
#pragma unroll
        for (int r = 0; r < 4; r++) {
            uint4 v = Es[(g << 2) + r];
            const __half2* h = reinterpret_cast<const __half2*>(&v);
            float2 f0 = __half22float2(h[0]);
            float2 f1 = __half22float2(h[1]);
            float2 f2 = __half22float2(h[2]);
            float2 f3 = __half22float2(h[3]);
            float dot = f0.x * bpf[0];
            dot = fmaf(f0.y, bpf[1], dot);
            dot = fmaf(f1.x, bpf[2], dot);
            dot = fmaf(f1.y, bpf[3], dot);
            dot = fmaf(f2.x, bpf[4], dot);
            dot = fmaf(f2.y, bpf[5], dot);
            dot = fmaf(f3.x, bpf[6], dot);
            float inv = rcpa(dot);
            of[r * 7 + 0] = f0.x * bf[0] * inv;
            of[r * 7 + 1] = f0.y * bf[1] * inv;
            of[r * 7 + 2] = f1.x * bf[2] * inv;
            of[r * 7 + 3] = f1.y * bf[3] * inv;
            of[r * 7 + 4] = f2.x * bf[4] * inv;
            of[r * 7 + 5] = f2.y * bf[5] * inv;
            of[r * 7 + 6] = f3.x * bf[6] * inv;
        }
        float4* od = reinterpret_cast<float4*>(out + (size_t)(base + (g << 2)) * K);
#pragma unroll
        for (int i = 0; i < 7; i++) od[i] = o[i];   // 4 rows = 7 STG.128
    }
}

// ---------------------------------------------------------------------------
extern "C" void kernel_launch(void* const* d_in, const int* in_sizes, int n_in,
                              void* d_out, int out_size) {
    const float* P = (const float*)d_in[0];
    float* out = (float*)d_out;
    (void)in_sizes; (void)n_in; (void)out_size;

    static int configured = 0;
    if (!configured) {
        cudaFuncSetAttribute(k_main, cudaFuncAttributeMaxDynamicSharedMemorySize,
                             (int)DYN_SMEM);
        configured = 1;
    }
    k_init<<<1, 512>>>();                       // reset barrier/reduction state
    k_main<<<GRID, TPB, DYN_SMEM>>>(P, out);    // everything else, one launch
}

// round 8
// speedup vs baseline: 2.5448x; 1.3894x over previous
#include <cuda_runtime.h>
#include <cuda_fp16.h>

#define NR   2097152
#define K    7
#define GRID 148                 // <= SM count: all blocks co-resident (1 CTA/SM via smem)
#define TPB  1024                // 32 warps: occupancy 50% (was 25%)
#define NW   (TPB / 32)
#define RPB  14172               // rows per block (mult of 4); last block: 13868
#define NIT  50

static __device__ float    g_S[NIT + 1][8];   // per-iteration fp32 reduction slots
static __device__ unsigned g_bar;             // grid barrier counter (monotonic)

// NR * Pb_j, exact products of the prior
__constant__ float c_NPb[K] = {
    (float)(2097152.0 * 0.17), (float)(2097152.0 * 0.14),
    (float)(2097152.0 * 0.15), (float)(2097152.0 * 0.12),
    (float)(2097152.0 * 0.05), (float)(2097152.0 * 0.13),
    (float)(2097152.0 * 0.24)
};

#define DYN_SMEM ((size_t)RPB * 16 + NW * K * sizeof(float))

// MUFU reciprocal (1 ulp)
__device__ __forceinline__ float rcpa(float x) {
    float y;
    asm("rcp.approx.f32 %0, %1;" : "=f"(y) : "f"(x));
    return y;
}

// ---------------------------------------------------------------------------
// Grid barrier: all GRID blocks resident, monotonic target. Volatile-load spin.
// ---------------------------------------------------------------------------
__device__ __forceinline__ void grid_bar(unsigned target) {
    __syncthreads();
    if (threadIdx.x == 0) {
        __threadfence();                       // release our g_S atomics
        atomicAdd(&g_bar, 1u);
        while (*(volatile unsigned*)&g_bar < target) { }
        __threadfence();                       // acquire side
    }
    __syncthreads();
}

// ---------------------------------------------------------------------------
// Block-reduce K fp32 partials -> float atomicAdd into g_S[it]
// ---------------------------------------------------------------------------
__device__ __forceinline__ void publish(float* swarp, float acc[K], int it) {
    int tid = threadIdx.x;
#pragma unroll
    for (int j = 0; j < K; j++) {
#pragma unroll
        for (int off = 16; off > 0; off >>= 1)
            acc[j] += __shfl_down_sync(0xffffffffu, acc[j], off);
    }
    int w = tid >> 5;
    if ((tid & 31) == 0) {
#pragma unroll
        for (int j = 0; j < K; j++) swarp[w * K + j] = acc[j];
    }
    __syncthreads();
    if (tid < K) {
        float s = 0.f;
#pragma unroll
        for (int ww = 0; ww < NW; ww++) s += swarp[ww * K + tid];
        atomicAdd(&g_S[it][tid], s);
    }
}

// ---------------------------------------------------------------------------
// Lane-parallel redundant b update: lane j<7 computes one component (one powf
// per lane instead of 7 per thread), shfl broadcasts. Returns err.
// ---------------------------------------------------------------------------
__device__ __forceinline__ float b_update(int it, float bf[K], float bpf[K]) {
    const float FI = (float)(1.0 / 1.1);
    int lane = threadIdx.x & 31;
    int jj = lane < K ? lane : 0;
    float S  = __ldcg(&g_S[it][jj]);           // L2 read (atomics live in L2)
    float v  = __fdividef(c_NPb[jj], S);       // b_j = Pb_j / (Q^T a)_j
    float nb = __powf(v, FI);                  // SEMI_USE exponent
    float e2 = 0.f;
#pragma unroll
    for (int j = 0; j < K; j++) {
        float nbj = __shfl_sync(0xffffffffu, nb, j);
        float d = nbj - bf[j];
        e2 = fmaf(d, d, e2);
        bpf[j] = bf[j];
        bf[j]  = nbj;
    }
    return sqrtf(e2);
}

// ---------------------------------------------------------------------------
__global__ void k_init() {
    int t = threadIdx.x;
    if (t == 0) g_bar = 0u;
    float* p = &g_S[0][0];
    for (int i = t; i < (NIT + 1) * 8; i += blockDim.x) p[i] = 0.f;
}

// ---------------------------------------------------------------------------
// One dot/rcp/accum step for a row held in a uint4 of 8 halves
// ---------------------------------------------------------------------------
__device__ __forceinline__ void row_step(uint4 v, const float bf[K], float acc[K]) {
    const __half2* h = reinterpret_cast<const __half2*>(&v);
    float2 f0 = __half22float2(h[0]);
    float2 f1 = __half22float2(h[1]);
    float2 f2 = __half22float2(h[2]);
    float2 f3 = __half22float2(h[3]);
    float dot = f0.x * bf[0];
    dot = fmaf(f0.y, bf[1], dot);
    dot = fmaf(f1.x, bf[2], dot);
    dot = fmaf(f1.y, bf[3], dot);
    dot = fmaf(f2.x, bf[4], dot);
    dot = fmaf(f2.y, bf[5], dot);
    dot = fmaf(f3.x, bf[6], dot);
    float inv = rcpa(dot);                 // row max of E is 1 -> dot > 0
    acc[0] = fmaf(f0.x, inv, acc[0]);
    acc[1] = fmaf(f0.y, inv, acc[1]);
    acc[2] = fmaf(f1.x, inv, acc[2]);
    acc[3] = fmaf(f1.y, inv, acc[3]);
    acc[4] = fmaf(f2.x, inv, acc[4]);
    acc[5] = fmaf(f2.y, inv, acc[5]);
    acc[6] = fmaf(f3.x, inv, acc[6]);
}

// ---------------------------------------------------------------------------
// Persistent fused kernel: pre + all Sinkhorn iterations + final plan.
// E (fp16, 16 B/row) lives in this block's SMEM for the whole run.
// ---------------------------------------------------------------------------
__global__ void __launch_bounds__(TPB, 1)
k_main(const float* __restrict__ P, float* __restrict__ out) {
    extern __shared__ __align__(16) unsigned char dyn[];
    uint4* Es    = reinterpret_cast<uint4*>(dyn);                 // [nrows]
    float* swarp = reinterpret_cast<float*>(dyn + (size_t)RPB * 16);

    const int tid   = threadIdx.x;
    const int base  = blockIdx.x * RPB;
    const int nrows = min(RPB, NR - base);
    const int ngrp  = nrows >> 2;          // groups of 4 rows (exact)
    unsigned phase = 0;

    float bf[K], bpf[K];
#pragma unroll
    for (int j = 0; j < K; j++) { bf[j] = 0.125f; bpf[j] = 0.125f; }

    // ---- Phase A: build E in SMEM + iteration-1 partials --------------------
    // Iter 1 closed form: w_i = 8 r_i / (r_i*sumE_i + 1), r_i = s1^-10
    float acc[K];
#pragma unroll
    for (int j = 0; j < K; j++) acc[j] = 0.f;

    for (int g = tid; g < ngrp; g += TPB) {
        const uint4* ps = reinterpret_cast<const uint4*>(P + (size_t)(base + (g << 2)) * K);
        uint4 q[7];
#pragma unroll
        for (int i = 0; i < 7; i++) q[i] = ps[i];   // 4 rows = 28 floats, coalesced
        const float* pf = reinterpret_cast<const float*>(q);
#pragma unroll
        for (int r = 0; r < 4; r++) {
            const float* pr = pf + r * 7;
            float m = pr[0];
#pragma unroll
            for (int j = 1; j < K; j++) m = fmaxf(m, pr[j]);
            float t[K], s1 = 0.f;
#pragma unroll
            for (int j = 0; j < K; j++) {
                t[j] = __expf(pr[j] - m);          // MUFU EX2
                s1 += t[j];
            }
            float E[K], sE = 0.f;
#pragma unroll
            for (int j = 0; j < K; j++) {
                float t2 = t[j] * t[j], t4 = t2 * t2, t8 = t4 * t4;
                E[j] = t8 * t2;                    // exp(10*(p-m)) = t^10
                sE += E[j];
            }
            __half2 h0 = __floats2half2_rn(E[0], E[1]);
            __half2 h1 = __floats2half2_rn(E[2], E[3]);
            __half2 h2 = __floats2half2_rn(E[4], E[5]);
            __half2 h3 = __floats2half2_rn(E[6], 0.f);
            uint4 u;
            u.x = *reinterpret_cast<unsigned*>(&h0);
            u.y = *reinterpret_cast<unsigned*>(&h1);
            u.z = *reinterpret_cast<unsigned*>(&h2);
            u.w = *reinterpret_cast<unsigned*>(&h3);
            Es[(g << 2) + r] = u;

            float s2 = s1 * s1, s4 = s2 * s2, s8 = s4 * s4;
            float r10 = rcpa(s8 * s2);                        // s1^-10
            float w = 8.f * r10 * rcpa(fmaf(r10, sE, 1.f));
#pragma unroll
            for (int j = 0; j < K; j++) acc[j] = fmaf(w, E[j], acc[j]);
        }
    }
    publish(swarp, acc, 1);
    grid_bar(GRID * (++phase));
    int it = 1;
    float err = b_update(1, bf, bpf);
    err = sqrtf(err * err + 0.015625f);    // b[7]: 1/8 -> 0 on iteration 1

    // ---- Iterations 2..50: SMEM-only passes, 4-way ILP ----------------------
    const int nmain = nrows & ~(4 * TPB - 1);   // 4*TPB = 4096, power of two
    while (err > 1e-6f && it < NIT) {
        it++;
        float a2[K];
#pragma unroll
        for (int j = 0; j < K; j++) a2[j] = 0.f;

        for (int idx = tid; idx < nmain; idx += 4 * TPB) {
            uint4 v0 = Es[idx];
            uint4 v1 = Es[idx + TPB];
            uint4 v2 = Es[idx + 2 * TPB];
            uint4 v3 = Es[idx + 3 * TPB];
            row_step(v0, bf, a2);
            row_step(v1, bf, a2);
            row_step(v2, bf, a2);
            row_step(v3, bf, a2);
        }
        for (int idx = nmain + tid; idx < nrows; idx += TPB)
            row_step(Es[idx], bf, a2);

        publish(swarp, a2, it);
        grid_bar(GRID * (++phase));
        err = b_update(it, bf, bpf);
    }

    // ---- Final: plan_ij = E_ij * bf_j / (E_i . bpf), from SMEM --------------
    for (int g = tid; g < ngrp; g += TPB) {
        float4 o[7];
        float* of = reinterpret_cast<float*>(o);
#pragma unroll
        for (int r = 0; r < 4; r++) {
            uint4 v = Es[(g << 2) + r];
            const __half2* h = reinterpret_cast<const __half2*>(&v);
            float2 f0 = __half22float2(h[0]);
            float2 f1 = __half22float2(h[1]);
            float2 f2 = __half22float2(h[2]);
            float2 f3 = __half22float2(h[3]);
            float dot = f0.x * bpf[0];
            dot = fmaf(f0.y, bpf[1], dot);
            dot = fmaf(f1.x, bpf[2], dot);
            dot = fmaf(f1.y, bpf[3], dot);
            dot = fmaf(f2.x, bpf[4], dot);
            dot = fmaf(f2.y, bpf[5], dot);
            dot = fmaf(f3.x, bpf[6], dot);
            float inv = rcpa(dot);
            of[r * 7 + 0] = f0.x * bf[0] * inv;
            of[r * 7 + 1] = f0.y * bf[1] * inv;
            of[r * 7 + 2] = f1.x * bf[2] * inv;
            of[r * 7 + 3] = f1.y * bf[3] * inv;
            of[r * 7 + 4] = f2.x * bf[4] * inv;
            of[r * 7 + 5] = f2.y * bf[5] * inv;
            of[r * 7 + 6] = f3.x * bf[6] * inv;
        }
        float4* od = reinterpret_cast<float4*>(out + (size_t)(base + (g << 2)) * K);
#pragma unroll
        for (int i = 0; i < 7; i++) od[i] = o[i];   // 4 rows = 7 STG.128
    }
}

// ---------------------------------------------------------------------------
extern "C" void kernel_launch(void* const* d_in, const int* in_sizes, int n_in,
                              void* d_out, int out_size) {
    const float* P = (const float*)d_in[0];
    float* out = (float*)d_out;
    (void)in_sizes; (void)n_in; (void)out_size;

    static int configured = 0;
    if (!configured) {
        cudaFuncSetAttribute(k_main, cudaFuncAttributeMaxDynamicSharedMemorySize,
                             (int)DYN_SMEM);
        configured = 1;
    }
    k_init<<<1, 512>>>();                       // reset barrier/reduction state
    k_main<<<GRID, TPB, DYN_SMEM>>>(P, out);    // everything else, one launch
}

// round 12
// speedup vs baseline: 2.6211x; 1.0300x over previous
#include <cuda_runtime.h>
#include <cuda_fp16.h>

#define NR   2097152
#define K    7
#define GRID 148                 // <= SM count: all blocks co-resident (1 CTA/SM via smem)
#define TPB  1024                // 32 warps
#define NW   (TPB / 32)
#define RPB  14172               // rows per block (mult of 4); last block: 13868
#define NIT  50

static __device__ float    g_S[NIT + 1][8];   // per-iteration fp32 reduction slots
static __device__ unsigned g_bar;             // grid barrier counter (monotonic)

// NR * Pb_j
__constant__ float c_NPb[K] = {
    (float)(2097152.0 * 0.17), (float)(2097152.0 * 0.14),
    (float)(2097152.0 * 0.15), (float)(2097152.0 * 0.12),
    (float)(2097152.0 * 0.05), (float)(2097152.0 * 0.13),
    (float)(2097152.0 * 0.24)
};

#define DYN_SMEM ((size_t)RPB * 16 + NW * K * sizeof(float))

// MUFU reciprocal (1 ulp)
__device__ __forceinline__ float rcpa(float x) {
    float y; asm("rcp.approx.f32 %0, %1;" : "=f"(y) : "f"(x)); return y;
}

// ---------------------------------------------------------------------------
// Grid barrier: all GRID blocks resident, monotonic target. Volatile-load spin.
// ---------------------------------------------------------------------------
__device__ __forceinline__ void grid_bar(unsigned target) {
    __syncthreads();
    if (threadIdx.x == 0) {
        __threadfence();                       // release our g_S atomics
        atomicAdd(&g_bar, 1u);
        while (*(volatile unsigned*)&g_bar < target) { }
        __threadfence();                       // acquire side
    }
    __syncthreads();
}

// ---------------------------------------------------------------------------
// Block-reduce K fp32 partials -> float atomicAdd into g_S[it]
// ---------------------------------------------------------------------------
__device__ __forceinline__ void publish(float* swarp, float acc[K], int it) {
    int tid = threadIdx.x;
#pragma unroll
    for (int j = 0; j < K; j++) {
#pragma unroll
        for (int off = 16; off > 0; off >>= 1)
            acc[j] += __shfl_down_sync(0xffffffffu, acc[j], off);
    }
    int w = tid >> 5;
    if ((tid & 31) == 0) {
#pragma unroll
        for (int j = 0; j < K; j++) swarp[w * K + j] = acc[j];
    }
    __syncthreads();
    if (tid < K) {
        float s = 0.f;
#pragma unroll
        for (int ww = 0; ww < NW; ww++) s += swarp[ww * K + tid];
        atomicAdd(&g_S[it][tid], s);
    }
}

// ---------------------------------------------------------------------------
// Lane-parallel redundant b update: lane j<7 computes one component (one powf
// per lane instead of 7 per thread), shfl broadcasts. Returns err.
// ---------------------------------------------------------------------------
__device__ __forceinline__ float b_update(int it, float bf[K], float bpf[K]) {
    const float FI = (float)(1.0 / 1.1);
    int lane = threadIdx.x & 31;
    int jj = lane < K ? lane : 0;
    float S  = __ldcg(&g_S[it][jj]);           // L2 read (atomics live in L2)
    float v  = __fdividef(c_NPb[jj], S);       // b_j = Pb_j / (Q^T a)_j
    float nb = __powf(v, FI);                  // SEMI_USE exponent
    float e2 = 0.f;
#pragma unroll
    for (int j = 0; j < K; j++) {
        float nbj = __shfl_sync(0xffffffffu, nb, j);
        float d = nbj - bf[j];
        e2 = fmaf(d, d, e2);
        bpf[j] = bf[j];
        bf[j]  = nbj;
    }
    return sqrtf(e2);
}

// ---------------------------------------------------------------------------
__global__ void k_init() {
    int t = threadIdx.x;
    if (t == 0) g_bar = 0u;
    float* p = &g_S[0][0];
    for (int i = t; i < (NIT + 1) * 8; i += blockDim.x) p[i] = 0.f;
}

// ---------------------------------------------------------------------------
// One dot/rcp/accum step, half2 arithmetic. Per-row fp16 rounding is zero-mean
// and averages out over the 2M-row T_j sums; rcp stays f32 MUFU (unbiased —
// bias would NOT average out). acc2 magnitudes <= ~60 (fp16 max 65504).
// ---------------------------------------------------------------------------
__device__ __forceinline__ void row_step16(uint4 v, const __half2 bh[4], __half2 acc2[4]) {
    const __half2* h = reinterpret_cast<const __half2*>(&v);
    __half2 h0 = h[0], h1 = h[1], h2 = h[2], h3 = h[3];
    __half2 d = __hmul2(h0, bh[0]);
    d = __hfma2(h1, bh[1], d);
    d = __hfma2(h2, bh[2], d);
    d = __hfma2(h3, bh[3], d);                 // bh[3] hi = 0 (pad col)
    float dot = __low2float(d) + __high2float(d);
    __half2 inv2 = __float2half2_rn(rcpa(dot)); // row max of E is 1 -> dot > 0
    acc2[0] = __hfma2(h0, inv2, acc2[0]);
    acc2[1] = __hfma2(h1, inv2, acc2[1]);
    acc2[2] = __hfma2(h2, inv2, acc2[2]);
    acc2[3] = __hfma2(h3, inv2, acc2[3]);
}

// ---------------------------------------------------------------------------
// Persistent fused kernel: pre + 50 Sinkhorn iterations + final plan.
// E (fp16, 16 B/row) lives in this block's SMEM for the whole run.
// ---------------------------------------------------------------------------
__global__ void __launch_bounds__(TPB, 1)
k_main(const float* __restrict__ P, float* __restrict__ out) {
    extern __shared__ __align__(16) unsigned char dyn[];
    uint4* Es    = reinterpret_cast<uint4*>(dyn);                 // [nrows]
    float* swarp = reinterpret_cast<float*>(dyn + (size_t)RPB * 16);

    const int tid   = threadIdx.x;
    const int base  = blockIdx.x * RPB;
    const int nrows = min(RPB, NR - base);
    const int ngrp  = nrows >> 2;          // groups of 4 rows (exact)
    unsigned phase = 0;

    float bf[K], bpf[K];
#pragma unroll
    for (int j = 0; j < K; j++) { bf[j] = 0.125f; bpf[j] = 0.125f; }

    // ---- Phase A: build E in SMEM + iteration-1 partials --------------------
    // Iter 1 closed form: w_i = 8 r_i / (r_i*sumE_i + 1), r_i = s1^-10
    float acc[K];
#pragma unroll
    for (int j = 0; j < K; j++) acc[j] = 0.f;

    for (int g = tid; g < ngrp; g += TPB) {
        const uint4* ps = reinterpret_cast<const uint4*>(P + (size_t)(base + (g << 2)) * K);
        uint4 q[7];
#pragma unroll
        for (int i = 0; i < 7; i++) q[i] = ps[i];   // 4 rows = 28 floats, coalesced
        const float* pf = reinterpret_cast<const float*>(q);
#pragma unroll
        for (int r = 0; r < 4; r++) {
            const float* pr = pf + r * 7;
            float m = pr[0];
#pragma unroll
            for (int j = 1; j < K; j++) m = fmaxf(m, pr[j]);
            float t[K], s1 = 0.f;
#pragma unroll
            for (int j = 0; j < K; j++) {
                t[j] = __expf(pr[j] - m);          // MUFU EX2
                s1 += t[j];
            }
            float E[K], sE = 0.f;
#pragma unroll
            for (int j = 0; j < K; j++) {
                float t2 = t[j] * t[j], t4 = t2 * t2, t8 = t4 * t4;
                E[j] = t8 * t2;                    // exp(10*(p-m)) = t^10
                sE += E[j];
            }
            __half2 h0 = __floats2half2_rn(E[0], E[1]);
            __half2 h1 = __floats2half2_rn(E[2], E[3]);
            __half2 h2 = __floats2half2_rn(E[4], E[5]);
            __half2 h3 = __floats2half2_rn(E[6], 0.f);
            uint4 u;
            u.x = *reinterpret_cast<unsigned*>(&h0);
            u.y = *reinterpret_cast<unsigned*>(&h1);
            u.z = *reinterpret_cast<unsigned*>(&h2);
            u.w = *reinterpret_cast<unsigned*>(&h3);
            Es[(g << 2) + r] = u;

            float s2 = s1 * s1, s4 = s2 * s2, s8 = s4 * s4;
            float r10 = rcpa(s8 * s2);                        // s1^-10
            float w = 8.f * r10 * rcpa(fmaf(r10, sE, 1.f));
#pragma unroll
            for (int j = 0; j < K; j++) acc[j] = fmaf(w, E[j], acc[j]);
        }
    }
    publish(swarp, acc, 1);
    grid_bar(GRID * (++phase));
    int it = 1;
    float err = b_update(1, bf, bpf);
    err = sqrtf(err * err + 0.015625f);    // b[7]: 1/8 -> 0 on iteration 1

    // ---- Iterations 2..50: SMEM-only half2 passes, 4-way ILP ----------------
    const int nmain = nrows & ~(4 * TPB - 1);   // 4*TPB = 4096, power of two
    while (err > 1e-6f && it < NIT) {
        it++;
        __half2 bh[4];
        bh[0] = __floats2half2_rn(bf[0], bf[1]);
        bh[1] = __floats2half2_rn(bf[2], bf[3]);
        bh[2] = __floats2half2_rn(bf[4], bf[5]);
        bh[3] = __floats2half2_rn(bf[6], 0.f);
        __half2 acc2[4];
        __half2 z = __floats2half2_rn(0.f, 0.f);
        acc2[0] = z; acc2[1] = z; acc2[2] = z; acc2[3] = z;

        for (int idx = tid; idx < nmain; idx += 4 * TPB) {
            uint4 v0 = Es[idx];
            uint4 v1 = Es[idx + TPB];
            uint4 v2 = Es[idx + 2 * TPB];
            uint4 v3 = Es[idx + 3 * TPB];
            row_step16(v0, bh, acc2);
            row_step16(v1, bh, acc2);
            row_step16(v2, bh, acc2);
            row_step16(v3, bh, acc2);
        }
        for (int idx = nmain + tid; idx < nrows; idx += TPB)
            row_step16(Es[idx], bh, acc2);

        float a2[K];
        a2[0] = __low2float(acc2[0]); a2[1] = __high2float(acc2[0]);
        a2[2] = __low2float(acc2[1]); a2[3] = __high2float(acc2[1]);
        a2[4] = __low2float(acc2[2]); a2[5] = __high2float(acc2[2]);
        a2[6] = __low2float(acc2[3]);              // hi half = pad, discarded
        publish(swarp, a2, it);
        grid_bar(GRID * (++phase));
        err = b_update(it, bf, bpf);
    }

    // ---- Final: plan_ij = E_ij * bf_j / (E_i . bpf), fp32 from SMEM ---------
    for (int g = tid; g < ngrp; g += TPB) {
        float4 o[7];
        float* of = reinterpret_cast<float*>(o);
#pragma unroll
        for (int r = 0; r < 4; r++) {
            uint4 v = Es[(g << 2) + r];
            const __half2* h = reinterpret_cast<const __half2*>(&v);
            float2 f0 = __half22float2(h[0]);
            float2 f1 = __half22float2(h[1]);
            float2 f2 = __half22float2(h[2]);
            float2 f3 = __half22float2(h[3]);
            float dot = f0.x * bpf[0];
            dot = fmaf(f0.y, bpf[1], dot);
            dot = fmaf(f1.x, bpf[2], dot);
            dot = fmaf(f1.y, bpf[3], dot);
            dot = fmaf(f2.x, bpf[4], dot);
            dot = fmaf(f2.y, bpf[5], dot);
            dot = fmaf(f3.x, bpf[6], dot);
            float inv = rcpa(dot);
            of[r * 7 + 0] = f0.x * bf[0] * inv;
            of[r * 7 + 1] = f0.y * bf[1] * inv;
            of[r * 7 + 2] = f1.x * bf[2] * inv;
            of[r * 7 + 3] = f1.y * bf[3] * inv;
            of[r * 7 + 4] = f2.x * bf[4] * inv;
            of[r * 7 + 5] = f2.y * bf[5] * inv;
            of[r * 7 + 6] = f3.x * bf[6] * inv;
        }
        float4* od = reinterpret_cast<float4*>(out + (size_t)(base + (g << 2)) * K);
#pragma unroll
        for (int i = 0; i < 7; i++) od[i] = o[i];   // 4 rows = 7 STG.128
    }
}

// ---------------------------------------------------------------------------
extern "C" void kernel_launch(void* const* d_in, const int* in_sizes, int n_in,
                              void* d_out, int out_size) {
    const float* P = (const float*)d_in[0];
    float* out = (float*)d_out;
    (void)in_sizes; (void)n_in; (void)out_size;

    static int configured = 0;
    if (!configured) {
        cudaFuncSetAttribute(k_main, cudaFuncAttributeMaxDynamicSharedMemorySize,
                             (int)DYN_SMEM);
        configured = 1;
    }
    k_init<<<1, 512>>>();                       // reset barrier/reduction state
    k_main<<<GRID, TPB, DYN_SMEM>>>(P, out);    // everything else, one launch
}

// round 14
// speedup vs baseline: 3.0077x; 1.1475x over previous
#include <cuda_runtime.h>
#include <cuda_fp16.h>

#define NR   2097152
#define K    7
#define GRID 148                 // <= SM count: all blocks co-resident (1 CTA/SM via smem)
#define TPB  1024                // 32 warps
#define NW   (TPB / 32)
#define RPB  14172               // rows per block (mult of 4); last block: 13868
#define NIT  50

static __device__ float    g_S[NIT + 1][8];   // per-iteration fp32 reduction slots
static __device__ unsigned g_bar;             // grid barrier counter (monotonic)

// NR * Pb_j
__constant__ float c_NPb[K] = {
    (float)(2097152.0 * 0.17), (float)(2097152.0 * 0.14),
    (float)(2097152.0 * 0.15), (float)(2097152.0 * 0.12),
    (float)(2097152.0 * 0.05), (float)(2097152.0 * 0.13),
    (float)(2097152.0 * 0.24)
};

#define DYN_SMEM ((size_t)RPB * 16 + (NW * K + 8) * sizeof(float))

// MUFU reciprocal (1 ulp)
__device__ __forceinline__ float rcpa(float x) {
    float y; asm("rcp.approx.f32 %0, %1;" : "=f"(y) : "f"(x)); return y;
}

// ---------------------------------------------------------------------------
// Block-reduce K fp32 partials -> float atomicAdd into g_S[it]
// ---------------------------------------------------------------------------
__device__ __forceinline__ void publish(float* swarp, float acc[K], int it) {
    int tid = threadIdx.x;
#pragma unroll
    for (int j = 0; j < K; j++) {
#pragma unroll
        for (int off = 16; off > 0; off >>= 1)
            acc[j] += __shfl_down_sync(0xffffffffu, acc[j], off);
    }
    int w = tid >> 5;
    if ((tid & 31) == 0) {
#pragma unroll
        for (int j = 0; j < K; j++) swarp[w * K + j] = acc[j];
    }
    __syncthreads();
    if (tid < K) {
        float s = 0.f;
#pragma unroll
        for (int ww = 0; ww < NW; ww++) s += swarp[ww * K + tid];
        atomicAdd(&g_S[it][tid], s);
    }
}

// ---------------------------------------------------------------------------
// Fused grid barrier + b update. RACE FIX vs round 13: ALL 32 lanes of warp 0
// spin on the barrier counter (each lane's own volatile load must observe the
// target before that lane's g_S read) — no reliance on warp reconvergence
// ordering under independent thread scheduling. Then warp 0 computes the 7
// powf, stores to SMEM; one syncthreads gates the whole block.
// ---------------------------------------------------------------------------
__device__ __forceinline__ void sync_update(int it, unsigned target, float* sb,
                                            float bf[K], float bpf[K]) {
    const float FI = (float)(1.0 / 1.1);
    __syncthreads();                       // all block atomics issued
    if (threadIdx.x < 32) {
        if (threadIdx.x == 0) {
            __threadfence();               // release our g_S contribution
            atomicAdd(&g_bar, 1u);
        }
        while (*(volatile unsigned*)&g_bar < target) { }   // every lane spins
        __threadfence();                   // acquire
        int jj = (threadIdx.x < K) ? threadIdx.x : 0;
        float S  = __ldcg(&g_S[it][jj]);
        float nb = __powf(__fdividef(c_NPb[jj], S), FI);
        if (threadIdx.x < K) sb[threadIdx.x] = nb;
    }
    __syncthreads();
#pragma unroll
    for (int j = 0; j < K; j++) { bpf[j] = bf[j]; bf[j] = sb[j]; }
}

// ---------------------------------------------------------------------------
__global__ void k_init() {
    int t = threadIdx.x;
    if (t == 0) g_bar = 0u;
    float* p = &g_S[0][0];
    for (int i = t; i < (NIT + 1) * 8; i += blockDim.x) p[i] = 0.f;
}

// ---------------------------------------------------------------------------
// One dot/rcp/accum step, all-fp16 chain: dot in half2, cross-lane fold via
// lowhigh swap + hadd2, MUFU fp16 reciprocal (~zero-mean error, averages out
// across the 2M-row T_j sums). acc2 <= ~350 << 65504.
// ---------------------------------------------------------------------------
__device__ __forceinline__ void row_step16(uint4 v, const __half2 bh[4], __half2 acc2[4]) {
    const __half2* h = reinterpret_cast<const __half2*>(&v);
    __half2 h0 = h[0], h1 = h[1], h2v = h[2], h3 = h[3];
    __half2 d = __hmul2(h0, bh[0]);
    d = __hfma2(h1, bh[1], d);
    d = __hfma2(h2v, bh[2], d);
    d = __hfma2(h3, bh[3], d);                 // bh[3] hi = 0 (pad col)
    __half2 ds = __hadd2(d, __lowhigh2highlow(d));   // {sum, sum}
    __half2 inv2 = h2rcp(ds);                  // fp16 MUFU rcp, both lanes
    acc2[0] = __hfma2(h0, inv2, acc2[0]);
    acc2[1] = __hfma2(h1, inv2, acc2[1]);
    acc2[2] = __hfma2(h2v, inv2, acc2[2]);
    acc2[3] = __hfma2(h3, inv2, acc2[3]);
}

// ---------------------------------------------------------------------------
// Persistent fused kernel: pre + 50 Sinkhorn iterations (exact count — the
// 1e-6 stop provably never fires: err49 ~ 0.125*0.909^48 ~ 1.3e-3) + final.
// E (fp16, 16 B/row) lives in this block's SMEM for the whole run.
// ---------------------------------------------------------------------------
__global__ void __launch_bounds__(TPB, 1)
k_main(const float* __restrict__ P, float* __restrict__ out) {
    extern __shared__ __align__(16) unsigned char dyn[];
    uint4* Es    = reinterpret_cast<uint4*>(dyn);                 // [nrows]
    float* swarp = reinterpret_cast<float*>(dyn + (size_t)RPB * 16);
    float* sb    = swarp + NW * K;                                // b broadcast

    const int tid   = threadIdx.x;
    const int base  = blockIdx.x * RPB;
    const int nrows = min(RPB, NR - base);
    const int ngrp  = nrows >> 2;          // groups of 4 rows (exact)

    float bf[K], bpf[K];
#pragma unroll
    for (int j = 0; j < K; j++) { bf[j] = 0.125f; bpf[j] = 0.125f; }

    // ---- Phase A: build E in SMEM + iteration-1 partials --------------------
    // Iter 1 closed form: w_i = 8 r_i / (r_i*sumE_i + 1), r_i = s1^-10
    float acc[K];
#pragma unroll
    for (int j = 0; j < K; j++) acc[j] = 0.f;

    for (int g = tid; g < ngrp; g += TPB) {
        const uint4* ps = reinterpret_cast<const uint4*>(P + (size_t)(base + (g << 2)) * K);
        uint4 q[7];
#pragma unroll
        for (int i = 0; i < 7; i++) q[i] = ps[i];   // 4 rows = 28 floats, coalesced
        const float* pf = reinterpret_cast<const float*>(q);
#pragma unroll
        for (int r = 0; r < 4; r++) {
            const float* pr = pf + r * 7;
            float m = pr[0];
#pragma unroll
            for (int j = 1; j < K; j++) m = fmaxf(m, pr[j]);
            float t[K], s1 = 0.f;
#pragma unroll
            for (int j = 0; j < K; j++) {
                t[j] = __expf(pr[j] - m);          // MUFU EX2
                s1 += t[j];
            }
            float E[K], sE = 0.f;
#pragma unroll
            for (int j = 0; j < K; j++) {
                float t2 = t[j] * t[j], t4 = t2 * t2, t8 = t4 * t4;
                E[j] = t8 * t2;                    // exp(10*(p-m)) = t^10
                sE += E[j];
            }
            __half2 h0 = __floats2half2_rn(E[0], E[1]);
            __half2 h1 = __floats2half2_rn(E[2], E[3]);
            __half2 h2 = __floats2half2_rn(E[4], E[5]);
            __half2 h3 = __floats2half2_rn(E[6], 0.f);
            uint4 u;
            u.x = *reinterpret_cast<unsigned*>(&h0);
            u.y = *reinterpret_cast<unsigned*>(&h1);
            u.z = *reinterpret_cast<unsigned*>(&h2);
            u.w = *reinterpret_cast<unsigned*>(&h3);
            Es[(g << 2) + r] = u;

            float s2 = s1 * s1, s4 = s2 * s2, s8 = s4 * s4;
            float r10 = rcpa(s8 * s2);                        // s1^-10
            float w = 8.f * r10 * rcpa(fmaf(r10, sE, 1.f));
#pragma unroll
            for (int j = 0; j < K; j++) acc[j] = fmaf(w, E[j], acc[j]);
        }
    }
    publish(swarp, acc, 1);
    sync_update(1, GRID, sb, bf, bpf);     // bf = b_1

    // ---- Iterations 2..50: SMEM-only half2 passes, 4-way ILP ----------------
    const int nmain = nrows & ~(4 * TPB - 1);   // 4*TPB = 4096, power of two
    for (int it = 2; it <= NIT; it++) {
        __half2 bh[4];
        bh[0] = __floats2half2_rn(bf[0], bf[1]);
        bh[1] = __floats2half2_rn(bf[2], bf[3]);
        bh[2] = __floats2half2_rn(bf[4], bf[5]);
        bh[3] = __floats2half2_rn(bf[6], 0.f);
        __half2 acc2[4];
        __half2 z = __floats2half2_rn(0.f, 0.f);
        acc2[0] = z; acc2[1] = z; acc2[2] = z; acc2[3] = z;

        for (int idx = tid; idx < nmain; idx += 4 * TPB) {
            uint4 v0 = Es[idx];
            uint4 v1 = Es[idx + TPB];
            uint4 v2 = Es[idx + 2 * TPB];
            uint4 v3 = Es[idx + 3 * TPB];
            row_step16(v0, bh, acc2);
            row_step16(v1, bh, acc2);
            row_step16(v2, bh, acc2);
            row_step16(v3, bh, acc2);
        }
        for (int idx = nmain + tid; idx < nrows; idx += TPB)
            row_step16(Es[idx], bh, acc2);

        float a2[K];
        a2[0] = __low2float(acc2[0]); a2[1] = __high2float(acc2[0]);
        a2[2] = __low2float(acc2[1]); a2[3] = __high2float(acc2[1]);
        a2[4] = __low2float(acc2[2]); a2[5] = __high2float(acc2[2]);
        a2[6] = __low2float(acc2[3]);              // hi half = pad, discarded
        publish(swarp, a2, it);
        sync_update(it, (unsigned)it * GRID, sb, bf, bpf);
    }

    // ---- Final: plan_ij = E_ij * bf_j / (E_i . bpf), fp32 from SMEM ---------
    for (int g = tid; g < ngrp; g += TPB) {
        float4 o[7];
        float* of = reinterpret_cast<float*>(o);
#pragma unroll
        for (int r = 0; r < 4; r++) {
            uint4 v = Es[(g << 2) + r];
            const __half2* h = reinterpret_cast<const __half2*>(&v);
            float2 f0 = __half22float2(h[0]);
            float2 f1 = __half22float2(h[1]);
            float2 f2 = __half22float2(h[2]);
            float2 f3 = __half22float2(h[3]);
            float dot = f0.x * bpf[0];
            dot = fmaf(f0.y, bpf[1], dot);
            dot = fmaf(f1.x, bpf[2], dot);
            dot = fmaf(f1.y, bpf[3], dot);
            dot = fmaf(f2.x, bpf[4], dot);
            dot = fmaf(f2.y, bpf[5], dot);
            dot = fmaf(f3.x, bpf[6], dot);
            float inv = rcpa(dot);
            of[r * 7 + 0] = f0.x * bf[0] * inv;
            of[r * 7 + 1] = f0.y * bf[1] * inv;
            of[r * 7 + 2] = f1.x * bf[2] * inv;
            of[r * 7 + 3] = f1.y * bf[3] * inv;
            of[r * 7 + 4] = f2.x * bf[4] * inv;
            of[r * 7 + 5] = f2.y * bf[5] * inv;
            of[r * 7 + 6] = f3.x * bf[6] * inv;
        }
        float4* od = reinterpret_cast<float4*>(out + (size_t)(base + (g << 2)) * K);
#pragma unroll
        for (int i = 0; i < 7; i++) od[i] = o[i];   // 4 rows = 7 STG.128
    }
}

// ---------------------------------------------------------------------------
extern "C" void kernel_launch(void* const* d_in, const int* in_sizes, int n_in,
                              void* d_out, int out_size) {
    const float* P = (const float*)d_in[0];
    float* out = (float*)d_out;
    (void)in_sizes; (void)n_in; (void)out_size;

    static int configured = 0;
    if (!configured) {
        cudaFuncSetAttribute(k_main, cudaFuncAttributeMaxDynamicSharedMemorySize,
                             (int)DYN_SMEM);
        configured = 1;
    }
    k_init<<<1, 512>>>();                       // reset barrier/reduction state
    k_main<<<GRID, TPB, DYN_SMEM>>>(P, out);    // everything else, one launch
}